// round 7
// baseline (speedup 1.0000x reference)
#include <cuda_runtime.h>
#include <cstdint>

#define N_NODES 4096
#define E_EDGES 262144
#define IN_DIM  256
#define NBOND   5
#define NATOM   16
#define LATENT  128

// Output layout (float32), tuple order (latent, atoms, bonds):
#define OFF_LATENT 0
#define OFF_ATOMS  524288
#define OFF_BONDS  589824

// ---------------------------------------------------------------------------
// Scratch
// ---------------------------------------------------------------------------
__device__ int   g_table[(size_t)N_NODES * N_NODES];   // 64 MB pair table
__device__ float g_s1[(size_t)N_NODES * IN_DIM];
__device__ int   g_jj[E_EDGES];
__device__ int   g_ii[E_EDGES];

// Packed fp32x2 helpers (FFMA2 — only reachable via PTX)
__device__ __forceinline__ void ffma2(unsigned long long& d,
                                      unsigned long long a, unsigned long long b) {
    asm("fma.rn.f32x2 %0, %1, %2, %0;" : "+l"(d) : "l"(a), "l"(b));
}
__device__ __forceinline__ float2 unpack2(unsigned long long v) {
    float2 r;
    asm("mov.b64 {%0, %1}, %2;" : "=f"(r.x), "=f"(r.y) : "l"(v));
    return r;
}
__device__ __forceinline__ unsigned long long pack2(float lo, float hi) {
    unsigned long long r;
    asm("mov.b64 %0, {%1, %2};" : "=l"(r) : "f"(lo), "f"(hi));
    return r;
}

// ---------------------------------------------------------------------------
// convert + clear, with per-block inline dtype detect (int64 little-endian
// with values < 4096 has all odd 32-bit words zero in the first 128 words).
// ---------------------------------------------------------------------------
__global__ void convert_clear_kernel(const void* __restrict__ eidx) {
    __shared__ int s_is64;
    if (threadIdx.x < 32) {
        const int* p = (const int*)eidx;
        int bad = (p[4 * threadIdx.x + 1] != 0) | (p[4 * threadIdx.x + 3] != 0);
        unsigned ab = __ballot_sync(0xffffffffu, bad);
        if (threadIdx.x == 0) s_is64 = (ab == 0u);
    }
    __syncthreads();
    int k = blockIdx.x * blockDim.x + threadIdx.x;
    if (k >= E_EDGES) return;
    int j, i;
    if (s_is64) {
        const long long* p = (const long long*)eidx;
        j = (int)p[k];
        i = (int)p[E_EDGES + k];
    } else {
        const int* p = (const int*)eidx;
        j = p[k];
        i = p[E_EDGES + k];
    }
    g_jj[k] = j;
    g_ii[k] = i;
    g_table[j * N_NODES + i] = -1;
    g_table[i * N_NODES + j] = -1;
}

// "Last write wins" scatter via atomicMax on edge index.
__global__ void scatter_kernel() {
    int k = blockIdx.x * blockDim.x + threadIdx.x;
    if (k >= E_EDGES) return;
    atomicMax(&g_table[g_jj[k] * N_NODES + g_ii[k]], k);
}

// ---------------------------------------------------------------------------
// Tiled SGEMM: C[m][t] = act( sum_k A[m][k] * W[t][k] + bias[t] )
// ---------------------------------------------------------------------------
template <int SILU, int SPLIT>
__global__ void __launch_bounds__(256)
gemm_kernel(const float* __restrict__ A_in, const float* __restrict__ W,
            const float* __restrict__ bias, float* __restrict__ out, int T) {
    __shared__ float As[16][64];
    __shared__ float Ws[16][64];

    const float* A = SPLIT ? g_s1 : A_in;

    int tid = threadIdx.x;
    int tn = tid & 15;
    int tm = tid >> 4;
    int m0 = blockIdx.y * 64;
    int t0 = blockIdx.x * 64;

    int lr = tid >> 2;
    int lc = (tid & 3) * 4;

    float acc[4][4] = {};

    for (int k0 = 0; k0 < IN_DIM; k0 += 16) {
        float4 av = *(const float4*)(A + (size_t)(m0 + lr) * IN_DIM + k0 + lc);
        As[lc + 0][lr] = av.x; As[lc + 1][lr] = av.y;
        As[lc + 2][lr] = av.z; As[lc + 3][lr] = av.w;

        float4 wv = make_float4(0.f, 0.f, 0.f, 0.f);
        if (t0 + lr < T)
            wv = *(const float4*)(W + (size_t)(t0 + lr) * IN_DIM + k0 + lc);
        Ws[lc + 0][lr] = wv.x; Ws[lc + 1][lr] = wv.y;
        Ws[lc + 2][lr] = wv.z; Ws[lc + 3][lr] = wv.w;

        __syncthreads();

        #pragma unroll
        for (int kk = 0; kk < 16; kk++) {
            float4 a = *(const float4*)&As[kk][tm * 4];
            float4 w = *(const float4*)&Ws[kk][tn * 4];
            acc[0][0] += a.x * w.x; acc[0][1] += a.x * w.y; acc[0][2] += a.x * w.z; acc[0][3] += a.x * w.w;
            acc[1][0] += a.y * w.x; acc[1][1] += a.y * w.y; acc[1][2] += a.y * w.z; acc[1][3] += a.y * w.w;
            acc[2][0] += a.z * w.x; acc[2][1] += a.z * w.y; acc[2][2] += a.z * w.z; acc[2][3] += a.z * w.w;
            acc[3][0] += a.w * w.x; acc[3][1] += a.w * w.y; acc[3][2] += a.w * w.z; acc[3][3] += a.w * w.w;
        }
        __syncthreads();
    }

    #pragma unroll
    for (int u = 0; u < 4; u++) {
        int m = m0 + tm * 4 + u;
        #pragma unroll
        for (int v = 0; v < 4; v++) {
            int t = t0 + tn * 4 + v;
            if (t < T) {
                float x = acc[u][v] + bias[t];
                if (SILU) x = x * __fdividef(1.f, 1.f + __expf(-x));
                if (!SPLIT) {
                    g_s1[(size_t)m * 256 + t] = x;
                } else {
                    if (t < NATOM)
                        out[OFF_ATOMS + (size_t)m * NATOM + t] = x;
                    else
                        out[OFF_LATENT + (size_t)m * LATENT + (t - NATOM)] = x;
                }
            }
        }
    }
}

// ---------------------------------------------------------------------------
// Edge head with FUSED esym, pipelined table lookups.
// 128 threads; thread t owns dims (2t, 2t+1).
//  - Threads 16..31 prefetch (j,i) two tiles ahead and table (f,r) one tile
//    ahead in registers; staged to smem at tile end (latency hidden by compute).
//  - esym staging: thread -> (edge b=t>>3, comp pair), dup-packed into esp.
//  - Phase A: 16 FFMA2 dot (esp broadcast LDS.128) + s1 LDG.64 gathers + silu
//    -> fbuf (conflict-free STS.64).
//  - Phase B: warp w owns q=w (warp0 also q=4); lane's 8-float weight slice in
//    registers; 2 conflict-free LDS.128 per edge; 5-level shuffle tree.
// ---------------------------------------------------------------------------
#define EB     16
#define NTILES 8
#define EPB    (EB * NTILES)

__global__ void __launch_bounds__(128)
edge_kernel(float* __restrict__ out_bonds, const float* __restrict__ e,
            const float* __restrict__ W_bond, const float* __restrict__ b_bond,
            const float* __restrict__ W_bonds, const float* __restrict__ b_bonds) {
    int t = threadIdx.x;
    int warp = t >> 5, lane = t & 31;

    // Phase-A weight pairs for dims (2t, 2t+1)
    unsigned long long wb2[16];
    #pragma unroll
    for (int c = 0; c < 16; c++)
        wb2[c] = pack2(W_bond[(2 * t) * 16 + c], W_bond[(2 * t + 1) * 16 + c]);
    float2 bb2 = ((const float2*)b_bond)[t];

    // Phase-B weights: warp w -> q=w; warp 0 additionally q=4
    float4 wA = *(const float4*)(W_bonds + warp * IN_DIM + lane * 4);
    float4 wB = *(const float4*)(W_bonds + warp * IN_DIM + 128 + lane * 4);
    float4 wA4 = make_float4(0.f, 0.f, 0.f, 0.f), wB4 = wA4;
    if (warp == 0) {
        wA4 = *(const float4*)(W_bonds + 4 * IN_DIM + lane * 4);
        wB4 = *(const float4*)(W_bonds + 4 * IN_DIM + 128 + lane * 4);
    }

    __shared__ int sj[2][EB], si[2][EB], sf[2][EB], sr[2][EB];
    __shared__ __align__(16) unsigned long long esp[EB][16];  // dup-packed esym
    __shared__ __align__(16) float fbuf[EB][IN_DIM];          // 16 KB

    int base0 = blockIdx.x * EPB;
    int u = t - 16;                 // prefetch-thread slot (valid for t in [16,32))
    int nj = 0, ni = 0, jj2 = 0, ii2 = 0;

    // Prologue: tile 0 indices + table to smem; tile 1 indices to regs.
    if (t < EB) {
        int j = g_jj[base0 + t], i = g_ii[base0 + t];
        sj[0][t] = j; si[0][t] = i;
        sf[0][t] = g_table[j * N_NODES + i];
        sr[0][t] = g_table[i * N_NODES + j];
    } else if (t < 2 * EB) {
        nj = g_jj[base0 + EB + u];
        ni = g_ii[base0 + EB + u];
    }
    __syncthreads();

    for (int tile = 0; tile < NTILES; tile++) {
        int buf = tile & 1, nbuf = buf ^ 1;
        int base = base0 + tile * EB;
        int nf = 0, nr = 0;
        bool pref = (t >= EB && t < 2 * EB && tile + 1 < NTILES);

        if (pref) {
            nf = g_table[nj * N_NODES + ni];      // tile n+1 table (in flight)
            nr = g_table[ni * N_NODES + nj];
            int idx2 = base + 2 * EB + u;         // tile n+2 indices
            if (idx2 >= E_EDGES) idx2 = E_EDGES - 1;
            jj2 = g_jj[idx2];
            ii2 = g_ii[idx2];
        }

        // esym staging: thread -> edge b=t>>3, comp pair c2=(t&7)*2
        {
            int b = t >> 3, c2 = (t & 7) * 2;
            int f = sf[buf][b], r = sr[buf][b];
            float2 vf = *(const float2*)(e + (size_t)f * 16 + c2);
            float vx, vy;
            if (r >= 0) {
                float2 vr = *(const float2*)(e + (size_t)r * 16 + c2);
                vx = 0.5f * (vf.x + vr.x); vy = 0.5f * (vf.y + vr.y);
            } else { vx = 0.5f * vf.x; vy = 0.5f * vf.y; }
            esp[b][c2]     = pack2(vx, vx);
            esp[b][c2 + 1] = pack2(vy, vy);
        }
        __syncthreads();

        // Phase A: batches of 4 edges, gathers issued up front
        #pragma unroll
        for (int b0 = 0; b0 < EB; b0 += 4) {
            float2 rj[4], ri[4];
            #pragma unroll
            for (int v = 0; v < 4; v++) {
                rj[v] = ((const float2*)(g_s1 + (size_t)sj[buf][b0 + v] * IN_DIM))[t];
                ri[v] = ((const float2*)(g_s1 + (size_t)si[buf][b0 + v] * IN_DIM))[t];
            }
            #pragma unroll
            for (int v = 0; v < 4; v++) {
                int b = b0 + v;
                unsigned long long acc = 0ull;
                const ulonglong2* ep = (const ulonglong2*)&esp[b][0];
                #pragma unroll
                for (int cc = 0; cc < 8; cc++) {
                    ulonglong2 pv = ep[cc];
                    ffma2(acc, pv.x, wb2[2 * cc]);
                    ffma2(acc, pv.y, wb2[2 * cc + 1]);
                }
                float2 a = unpack2(acc);
                float x0 = a.x + rj[v].x + ri[v].x + bb2.x;
                float x1 = a.y + rj[v].y + ri[v].y + bb2.y;
                float f0 = __fdividef(x0, 1.f + __expf(-x0));
                float f1 = __fdividef(x1, 1.f + __expf(-x1));
                *(float2*)&fbuf[b][2 * t] = make_float2(f0, f1);
            }
        }
        __syncthreads();

        // Phase B: warp w -> q=w; warp 0 also handles q=4. Weights in regs.
        #pragma unroll 4
        for (int b = 0; b < EB; b++) {
            float4 fa = *(const float4*)&fbuf[b][lane * 4];
            float4 fb = *(const float4*)&fbuf[b][128 + lane * 4];
            float p = fa.x * wA.x + fa.y * wA.y + fa.z * wA.z + fa.w * wA.w
                    + fb.x * wB.x + fb.y * wB.y + fb.z * wB.z + fb.w * wB.w;
            #pragma unroll
            for (int off = 16; off > 0; off >>= 1)
                p += __shfl_xor_sync(0xffffffffu, p, off);
            if (lane == 0)
                out_bonds[(size_t)(base + b) * NBOND + warp] = p + b_bonds[warp];
            if (warp == 0) {
                float p4 = fa.x * wA4.x + fa.y * wA4.y + fa.z * wA4.z + fa.w * wA4.w
                         + fb.x * wB4.x + fb.y * wB4.y + fb.z * wB4.z + fb.w * wB4.w;
                #pragma unroll
                for (int off = 16; off > 0; off >>= 1)
                    p4 += __shfl_xor_sync(0xffffffffu, p4, off);
                if (lane == 0)
                    out_bonds[(size_t)(base + b) * NBOND + 4] = p4 + b_bonds[4];
            }
        }

        // Stage next tile's prefetched indices/table results (loads have had
        // a full tile of compute to land — minimal stall here).
        if (pref) {
            sj[nbuf][u] = nj; si[nbuf][u] = ni;
            sf[nbuf][u] = nf; sr[nbuf][u] = nr;
            nj = jj2; ni = ii2;
        }
        __syncthreads();
    }
}

// ---------------------------------------------------------------------------
// Launch. Single stream; edge_kernel is launch #4 (the one ncu captures).
// ---------------------------------------------------------------------------
extern "C" void kernel_launch(void* const* d_in, const int* in_sizes, int n_in,
                              void* d_out, int out_size) {
    const float* s        = (const float*)d_in[0];
    const float* e        = (const float*)d_in[1];
    // d_in[2] = batch (unused)
    const void*  eidx     = d_in[3];
    const float* W_shared = (const float*)d_in[4];
    const float* b_shared = (const float*)d_in[5];
    const float* W_bond   = (const float*)d_in[6];
    const float* b_bond   = (const float*)d_in[7];
    const float* W_bonds  = (const float*)d_in[8];
    const float* b_bonds  = (const float*)d_in[9];
    const float* W_atoms  = (const float*)d_in[10];
    const float* b_atoms  = (const float*)d_in[11];
    float* out = (float*)d_out;

    const int tpb = 256;
    const int eblocks = E_EDGES / tpb;   // 1024

    convert_clear_kernel<<<eblocks, tpb>>>(eidx);                               // 1
    scatter_kernel<<<eblocks, tpb>>>();                                         // 2
    gemm_kernel<1, 0><<<dim3(4, 64), 256>>>(s, W_shared, b_shared, out, 256);   // 3
    edge_kernel<<<E_EDGES / EPB, 128>>>(out + OFF_BONDS, e,                     // 4
                                        W_bond, b_bond, W_bonds, b_bonds);
    gemm_kernel<0, 1><<<dim3(3, 64), 256>>>(nullptr, W_atoms, b_atoms, out, 144); // 5
}

// round 8
// speedup vs baseline: 1.4559x; 1.4559x over previous
#include <cuda_runtime.h>
#include <cstdint>

#define N_NODES 4096
#define E_EDGES 262144
#define IN_DIM  256
#define NBOND   5
#define NATOM   16
#define LATENT  128

// Output layout (float32), tuple order (latent, atoms, bonds):
#define OFF_LATENT 0
#define OFF_ATOMS  524288
#define OFF_BONDS  589824

// ---------------------------------------------------------------------------
// Scratch
// ---------------------------------------------------------------------------
__device__ int   g_table[(size_t)N_NODES * N_NODES];   // 64 MB pair table
__device__ float g_s1[(size_t)N_NODES * IN_DIM];
__device__ int   g_jj[E_EDGES];
__device__ int   g_ii[E_EDGES];

// ---------------------------------------------------------------------------
// convert + clear (2 edges/thread), with per-block inline dtype detect.
// ---------------------------------------------------------------------------
__global__ void convert_clear_kernel(const void* __restrict__ eidx) {
    __shared__ int s_is64;
    if (threadIdx.x < 32) {
        const int* p = (const int*)eidx;
        int bad = (p[4 * threadIdx.x + 1] != 0) | (p[4 * threadIdx.x + 3] != 0);
        unsigned ab = __ballot_sync(0xffffffffu, bad);
        if (threadIdx.x == 0) s_is64 = (ab == 0u);
    }
    __syncthreads();
    int k0 = (blockIdx.x * blockDim.x + threadIdx.x) * 2;
    if (k0 >= E_EDGES) return;
    int j0, i0, j1, i1;
    if (s_is64) {
        const long long* p = (const long long*)eidx;
        j0 = (int)p[k0];     i0 = (int)p[E_EDGES + k0];
        j1 = (int)p[k0 + 1]; i1 = (int)p[E_EDGES + k0 + 1];
    } else {
        const int* p = (const int*)eidx;
        j0 = p[k0];     i0 = p[E_EDGES + k0];
        j1 = p[k0 + 1]; i1 = p[E_EDGES + k0 + 1];
    }
    g_jj[k0] = j0;     g_ii[k0] = i0;
    g_jj[k0 + 1] = j1; g_ii[k0 + 1] = i1;
    g_table[j0 * N_NODES + i0] = -1;
    g_table[i0 * N_NODES + j0] = -1;
    g_table[j1 * N_NODES + i1] = -1;
    g_table[i1 * N_NODES + j1] = -1;
}

// "Last write wins" scatter via atomicMax on edge index.
__global__ void scatter_kernel() {
    int k = blockIdx.x * blockDim.x + threadIdx.x;
    if (k >= E_EDGES) return;
    atomicMax(&g_table[g_jj[k] * N_NODES + g_ii[k]], k);
}

// ---------------------------------------------------------------------------
// Tiled SGEMM: C[m][t] = act( sum_k A[m][k] * W[t][k] + bias[t] )
// ---------------------------------------------------------------------------
template <int SILU, int SPLIT>
__global__ void __launch_bounds__(256)
gemm_kernel(const float* __restrict__ A_in, const float* __restrict__ W,
            const float* __restrict__ bias, float* __restrict__ out, int T) {
    __shared__ float As[16][64];
    __shared__ float Ws[16][64];

    const float* A = SPLIT ? g_s1 : A_in;

    int tid = threadIdx.x;
    int tn = tid & 15;
    int tm = tid >> 4;
    int m0 = blockIdx.y * 64;
    int t0 = blockIdx.x * 64;

    int lr = tid >> 2;
    int lc = (tid & 3) * 4;

    float acc[4][4] = {};

    for (int k0 = 0; k0 < IN_DIM; k0 += 16) {
        float4 av = *(const float4*)(A + (size_t)(m0 + lr) * IN_DIM + k0 + lc);
        As[lc + 0][lr] = av.x; As[lc + 1][lr] = av.y;
        As[lc + 2][lr] = av.z; As[lc + 3][lr] = av.w;

        float4 wv = make_float4(0.f, 0.f, 0.f, 0.f);
        if (t0 + lr < T)
            wv = *(const float4*)(W + (size_t)(t0 + lr) * IN_DIM + k0 + lc);
        Ws[lc + 0][lr] = wv.x; Ws[lc + 1][lr] = wv.y;
        Ws[lc + 2][lr] = wv.z; Ws[lc + 3][lr] = wv.w;

        __syncthreads();

        #pragma unroll
        for (int kk = 0; kk < 16; kk++) {
            float4 a = *(const float4*)&As[kk][tm * 4];
            float4 w = *(const float4*)&Ws[kk][tn * 4];
            acc[0][0] += a.x * w.x; acc[0][1] += a.x * w.y; acc[0][2] += a.x * w.z; acc[0][3] += a.x * w.w;
            acc[1][0] += a.y * w.x; acc[1][1] += a.y * w.y; acc[1][2] += a.y * w.z; acc[1][3] += a.y * w.w;
            acc[2][0] += a.z * w.x; acc[2][1] += a.z * w.y; acc[2][2] += a.z * w.z; acc[2][3] += a.z * w.w;
            acc[3][0] += a.w * w.x; acc[3][1] += a.w * w.y; acc[3][2] += a.w * w.z; acc[3][3] += a.w * w.w;
        }
        __syncthreads();
    }

    #pragma unroll
    for (int u = 0; u < 4; u++) {
        int m = m0 + tm * 4 + u;
        #pragma unroll
        for (int v = 0; v < 4; v++) {
            int t = t0 + tn * 4 + v;
            if (t < T) {
                float x = acc[u][v] + bias[t];
                if (SILU) x = x * __fdividef(1.f, 1.f + __expf(-x));
                if (!SPLIT) {
                    g_s1[(size_t)m * 256 + t] = x;
                } else {
                    if (t < NATOM)
                        out[OFF_ATOMS + (size_t)m * NATOM + t] = x;
                    else
                        out[OFF_LATENT + (size_t)m * LATENT + (t - NATOM)] = x;
                }
            }
        }
    }
}

// ---------------------------------------------------------------------------
// Edge head with fused esym.
// 256 threads (8 warps); EB=32 edges/tile.
// Phase A (thread t = dim t): f = silu(s1[j]+s1[i]+esym.Wbond^T+b) -> fbuf
//   (FPAD=257: conflict-free rows AND columns). Scalar LDG.32 gathers.
// Phase B (lane-per-edge GEMM): warp w owns k-chunk [32w,32w+32); lane = edge;
//   reads fbuf column-wise (conflict-free via pad 257), weights broadcast from
//   smem; 5 accumulators/lane; partials -> pacc; 160-thread finalize.
// Table/index prefetch double-buffered in warp 0 registers.
// ---------------------------------------------------------------------------
#define EB     32
#define NTILES 4
#define EPB    (EB * NTILES)
#define FPAD   257

__global__ void __launch_bounds__(256, 4)
edge_kernel(float* __restrict__ out_bonds, const float* __restrict__ e,
            const float* __restrict__ W_bond, const float* __restrict__ b_bond,
            const float* __restrict__ W_bonds, const float* __restrict__ b_bonds) {
    int t = threadIdx.x;
    int warp = t >> 5, lane = t & 31;

    // Phase-A weights: W_bond row for dim t
    float wb[16];
    #pragma unroll
    for (int c = 0; c < 16; c += 4) {
        float4 v = *(const float4*)(W_bond + t * 16 + c);
        wb[c] = v.x; wb[c + 1] = v.y; wb[c + 2] = v.z; wb[c + 3] = v.w;
    }
    float bbias = b_bond[t];

    __shared__ int sj[2][EB], si[2][EB], sf[2][EB], sr[2][EB];       // 1 KB
    __shared__ __align__(16) float es[EB][16];                        // 2 KB
    __shared__ __align__(16) float fbuf[EB][FPAD];                    // 32.9 KB
    __shared__ __align__(16) float4 wq4[IN_DIM];                      // 4 KB (q0..3)
    __shared__ float wq1[IN_DIM];                                     // 1 KB (q4)
    __shared__ float pacc[8][EB][NBOND];                              // 5 KB

    // W_bonds -> smem transposed: wq4[c] = {W[0][c],W[1][c],W[2][c],W[3][c]}
    {
        float v0 = W_bonds[0 * IN_DIM + t];
        float v1 = W_bonds[1 * IN_DIM + t];
        float v2 = W_bonds[2 * IN_DIM + t];
        float v3 = W_bonds[3 * IN_DIM + t];
        wq4[t] = make_float4(v0, v1, v2, v3);
        wq1[t] = W_bonds[4 * IN_DIM + t];
    }

    int base0 = blockIdx.x * EPB;
    int nj = 0, ni = 0, jj2 = 0, ii2 = 0;

    // Prologue (warp 0, lane = edge slot): tile0 -> smem buf0; tile1 idx -> regs
    if (warp == 0) {
        int j = g_jj[base0 + lane], i = g_ii[base0 + lane];
        sj[0][lane] = j; si[0][lane] = i;
        sf[0][lane] = g_table[j * N_NODES + i];
        sr[0][lane] = g_table[i * N_NODES + j];
        if (NTILES > 1) {
            nj = g_jj[base0 + EB + lane];
            ni = g_ii[base0 + EB + lane];
        }
    }
    __syncthreads();

    for (int tile = 0; tile < NTILES; tile++) {
        int buf = tile & 1, nbuf = buf ^ 1;
        int base = base0 + tile * EB;
        int nf = 0, nr = 0;
        bool pref = (warp == 0) && (tile + 1 < NTILES);

        if (pref) {
            nf = g_table[nj * N_NODES + ni];      // tile+1 table (in flight)
            nr = g_table[ni * N_NODES + nj];
            int idx2 = base + 2 * EB + lane;      // tile+2 indices
            if (idx2 >= E_EDGES) idx2 = E_EDGES - 1;
            jj2 = g_jj[idx2];
            ii2 = g_ii[idx2];
        }

        // esym staging: thread -> edge b=t>>3, comps (c2, c2+1)
        {
            int b = t >> 3, c2 = (t & 7) * 2;
            int f = sf[buf][b], r = sr[buf][b];
            float2 vf = *(const float2*)(e + (size_t)f * 16 + c2);
            float vx, vy;
            if (r >= 0) {
                float2 vr = *(const float2*)(e + (size_t)r * 16 + c2);
                vx = 0.5f * (vf.x + vr.x); vy = 0.5f * (vf.y + vr.y);
            } else { vx = 0.5f * vf.x; vy = 0.5f * vf.y; }
            *(float2*)&es[b][c2] = make_float2(vx, vy);
        }
        __syncthreads();

        // Phase A: batches of 4 edges, scalar coalesced gathers
        #pragma unroll
        for (int b0 = 0; b0 < EB; b0 += 4) {
            float rj[4], ri[4];
            #pragma unroll
            for (int v = 0; v < 4; v++) {
                rj[v] = g_s1[(size_t)sj[buf][b0 + v] * IN_DIM + t];
                ri[v] = g_s1[(size_t)si[buf][b0 + v] * IN_DIM + t];
            }
            #pragma unroll
            for (int v = 0; v < 4; v++) {
                int b = b0 + v;
                float4 e0 = *(const float4*)&es[b][0];
                float4 e1 = *(const float4*)&es[b][4];
                float4 e2 = *(const float4*)&es[b][8];
                float4 e3 = *(const float4*)&es[b][12];

                float acc = bbias + rj[v] + ri[v];
                acc += e0.x * wb[0]  + e0.y * wb[1]  + e0.z * wb[2]  + e0.w * wb[3];
                acc += e1.x * wb[4]  + e1.y * wb[5]  + e1.z * wb[6]  + e1.w * wb[7];
                acc += e2.x * wb[8]  + e2.y * wb[9]  + e2.z * wb[10] + e2.w * wb[11];
                acc += e3.x * wb[12] + e3.y * wb[13] + e3.z * wb[14] + e3.w * wb[15];

                fbuf[b][t] = __fdividef(acc, 1.f + __expf(-acc));
            }
        }
        __syncthreads();

        // Phase B: warp w -> k-chunk [32w, 32w+32), lane = edge.
        {
            const float* fr = &fbuf[lane][warp * 32];
            float a0 = 0.f, a1 = 0.f, a2 = 0.f, a3 = 0.f, a4 = 0.f;
            #pragma unroll
            for (int c = 0; c < 32; c++) {
                float  fv = fr[c];                 // conflict-free (pad 257)
                float4 w4 = wq4[warp * 32 + c];    // broadcast
                float  w1 = wq1[warp * 32 + c];    // broadcast
                a0 += fv * w4.x; a1 += fv * w4.y; a2 += fv * w4.z;
                a3 += fv * w4.w; a4 += fv * w1;
            }
            pacc[warp][lane][0] = a0; pacc[warp][lane][1] = a1;
            pacc[warp][lane][2] = a2; pacc[warp][lane][3] = a3;
            pacc[warp][lane][4] = a4;
        }
        __syncthreads();

        // Finalize: 160 threads, thread -> (b = t/5, q = t%5); coalesced STG.
        if (t < EB * NBOND) {
            int b = t / NBOND, q = t - b * NBOND;
            float ssum = b_bonds[q];
            #pragma unroll
            for (int w = 0; w < 8; w++) ssum += pacc[w][b][q];
            out_bonds[(size_t)(base + b) * NBOND + q] = ssum;
        }

        // Stage prefetched next-tile data (loads have had a tile to land)
        if (pref) {
            sj[nbuf][lane] = nj; si[nbuf][lane] = ni;
            sf[nbuf][lane] = nf; sr[nbuf][lane] = nr;
            nj = jj2; ni = ii2;
        }
        __syncthreads();
    }
}

// ---------------------------------------------------------------------------
// Launch. edge_kernel is launch #4 (the one ncu captures).
// ---------------------------------------------------------------------------
extern "C" void kernel_launch(void* const* d_in, const int* in_sizes, int n_in,
                              void* d_out, int out_size) {
    const float* s        = (const float*)d_in[0];
    const float* e        = (const float*)d_in[1];
    // d_in[2] = batch (unused)
    const void*  eidx     = d_in[3];
    const float* W_shared = (const float*)d_in[4];
    const float* b_shared = (const float*)d_in[5];
    const float* W_bond   = (const float*)d_in[6];
    const float* b_bond   = (const float*)d_in[7];
    const float* W_bonds  = (const float*)d_in[8];
    const float* b_bonds  = (const float*)d_in[9];
    const float* W_atoms  = (const float*)d_in[10];
    const float* b_atoms  = (const float*)d_in[11];
    float* out = (float*)d_out;

    const int tpb = 256;

    convert_clear_kernel<<<E_EDGES / (2 * tpb), tpb>>>(eidx);                   // 1
    scatter_kernel<<<E_EDGES / tpb, tpb>>>();                                   // 2
    gemm_kernel<1, 0><<<dim3(4, 64), 256>>>(s, W_shared, b_shared, out, 256);   // 3
    edge_kernel<<<E_EDGES / EPB, 256>>>(out + OFF_BONDS, e,                     // 4
                                        W_bond, b_bond, W_bonds, b_bonds);
    gemm_kernel<0, 1><<<dim3(3, 64), 256>>>(nullptr, W_atoms, b_atoms, out, 144); // 5
}